// round 7
// baseline (speedup 1.0000x reference)
#include <cuda_runtime.h>
#include <cuda_bf16.h>
#include <cuda_fp8.h>
#include <cstdint>
#include <math.h>

// NT-Xent loss via FP8 (e4m3) mma.sync m16n8k32 + fused logsumexp epilogue.
// sim = 2*(z z^T), z (16384,128) f32 unit rows.
// loss_i = -sim_exact[i, i^8192] + 2 + log(sum_{j!=i} exp(sim_fp8[i,j]-2)).
// Positives computed exactly in f32 by a separate kernel; diagonal skipped exactly.

#define N2 16384
#define DIM 128
#define NTILES 128
#define ROWB 144                  // 128 fp8 bytes + 16 pad
#define TILE_B 18432              // 128*144
#define A_OFF 0
#define B0_OFF 18432
#define B1_OFF 36864
#define RBUF_OFF 55296            // 4*128 floats
#define SMEM_BYTES 57344

__device__ unsigned char g_zf8[N2 * DIM];   // 2 MB fp8 copy
__device__ float g_pos[N2];
__device__ float g_partials[NTILES];

__device__ __forceinline__ uint32_t smem_u32(const void* p) {
    uint32_t a;
    asm("{ .reg .u64 t; cvta.to.shared.u64 t, %1; cvt.u32.u64 %0, t; }" : "=r"(a) : "l"(p));
    return a;
}
__device__ __forceinline__ void cp16(uint32_t dst, const void* src) {
    asm volatile("cp.async.cg.shared.global [%0], [%1], 16;" :: "r"(dst), "l"(src));
}
__device__ __forceinline__ void ldm_x4(uint32_t (&r)[4], uint32_t addr) {
    asm volatile("ldmatrix.sync.aligned.m8n8.x4.shared.b16 {%0,%1,%2,%3}, [%4];"
                 : "=r"(r[0]), "=r"(r[1]), "=r"(r[2]), "=r"(r[3]) : "r"(addr));
}
__device__ __forceinline__ void mma_fp8(float (&c)[4], const uint32_t (&a)[4],
                                        uint32_t b0, uint32_t b1) {
    asm volatile("mma.sync.aligned.m16n8k32.row.col.f32.e4m3.e4m3.f32 "
                 "{%0,%1,%2,%3},{%4,%5,%6,%7},{%8,%9},{%0,%1,%2,%3};"
                 : "+f"(c[0]), "+f"(c[1]), "+f"(c[2]), "+f"(c[3])
                 : "r"(a[0]), "r"(a[1]), "r"(a[2]), "r"(a[3]), "r"(b0), "r"(b1));
}
__device__ __forceinline__ float ex2(float x) {
    float y; asm("ex2.approx.f32 %0, %1;" : "=f"(y) : "f"(x)); return y;
}
#define C1 2.885390081777927f     // 2*log2(e)

// ---- f32 -> e4m3 conversion (8 elems/thread) ----
__global__ void __launch_bounds__(256) convert_fp8_kernel(const float* __restrict__ z) {
    int i = blockIdx.x * blockDim.x + threadIdx.x;
    const float4 v0 = ((const float4*)z)[2 * i];
    const float4 v1 = ((const float4*)z)[2 * i + 1];
    uint32_t p0 = __nv_cvt_float2_to_fp8x2(make_float2(v0.x, v0.y), __NV_SATFINITE, __NV_E4M3);
    uint32_t p1 = __nv_cvt_float2_to_fp8x2(make_float2(v0.z, v0.w), __NV_SATFINITE, __NV_E4M3);
    uint32_t p2 = __nv_cvt_float2_to_fp8x2(make_float2(v1.x, v1.y), __NV_SATFINITE, __NV_E4M3);
    uint32_t p3 = __nv_cvt_float2_to_fp8x2(make_float2(v1.z, v1.w), __NV_SATFINITE, __NV_E4M3);
    uint2 o;
    o.x = (p0 & 0xffffu) | (p1 << 16);
    o.y = (p2 & 0xffffu) | (p3 << 16);
    ((uint2*)g_zf8)[i] = o;
}

// ---- exact f32 positives: pos[i] = 2*dot(z_i, z_{i^8192}) ----
__global__ void __launch_bounds__(256) pos_kernel(const float* __restrict__ z) {
    int row = (blockIdx.x * 256 + threadIdx.x) >> 5;
    int l = threadIdx.x & 31;
    float4 a = ((const float4*)(z + (size_t)row * DIM))[l];
    float4 b = ((const float4*)(z + (size_t)(row ^ 8192) * DIM))[l];
    float d = fmaf(a.x, b.x, fmaf(a.y, b.y, fmaf(a.z, b.z, a.w * b.w)));
    #pragma unroll
    for (int off = 16; off >= 1; off >>= 1)
        d += __shfl_xor_sync(0xffffffffu, d, off);
    if (l == 0) g_pos[row] = 2.f * d;
}

__device__ __forceinline__ void prefetch_tile(uint32_t smbase, const char* gsrc, int tid) {
    #pragma unroll
    for (int i = 0; i < 4; i++) {
        int c = tid + i * 256;                 // 1024 chunks of 16B
        int r = c >> 3, kc = c & 7;
        cp16(smbase + r * ROWB + kc * 16, gsrc + r * 128 + kc * 16);
    }
}

__global__ void __launch_bounds__(256, 1) ntxent_fp8_kernel() {
    extern __shared__ char sm[];
    const uint32_t s = smem_u32(sm);
    float* Rbuf = (float*)(sm + RBUF_OFF);     // [4 wn][128 rows]

    const int bi = blockIdx.x;
    const int tid = threadIdx.x;
    const int w = tid >> 5, l = tid & 31;
    const int wm = w >> 2, wn = w & 3;         // 2 (m) x 4 (n) warps

    const char* zf8 = (const char*)g_zf8;      // 16384 bytes per 128-row tile

    prefetch_tile(s + A_OFF, zf8 + (size_t)bi * 16384, tid);
    prefetch_tile(s + B0_OFF, zf8, tid);
    asm volatile("cp.async.commit_group;" ::: "memory");

    const uint32_t laneA = (uint32_t)((l & 15) * ROWB + (l >> 4) * 16);
    const uint32_t laneB = (uint32_t)(((l & 7) + ((l >> 4) << 3)) * ROWB + (((l >> 3) & 1) << 4));
    const uint32_t A_warp = s + A_OFF + (uint32_t)wm * 64 * ROWB + laneA;

    float rs[8];
    #pragma unroll
    for (int u = 0; u < 8; u++) rs[u] = 0.f;

    for (int jt = 0; jt < NTILES; jt++) {
        __syncthreads();
        if (jt + 1 < NTILES)
            prefetch_tile(s + ((jt & 1) ? B0_OFF : B1_OFF),
                          zf8 + (size_t)(jt + 1) * 16384, tid);
        asm volatile("cp.async.commit_group;" ::: "memory");
        asm volatile("cp.async.wait_group 1;" ::: "memory");
        __syncthreads();

        const uint32_t B_warp = s + ((jt & 1) ? B1_OFF : B0_OFF)
                                  + (uint32_t)wn * 32 * ROWB + laneB;

        float acc[4][4][4];
        #pragma unroll
        for (int mf = 0; mf < 4; mf++)
            #pragma unroll
            for (int nf = 0; nf < 4; nf++)
                #pragma unroll
                for (int q = 0; q < 4; q++) acc[mf][nf][q] = 0.f;

        #pragma unroll
        for (int ks = 0; ks < 4; ks++) {       // 4 x k32 covers K=128
            uint32_t a[4][4], b[2][4];
            #pragma unroll
            for (int mf = 0; mf < 4; mf++)
                ldm_x4(a[mf], A_warp + mf * (16 * ROWB) + ks * 32);
            #pragma unroll
            for (int nh = 0; nh < 2; nh++)
                ldm_x4(b[nh], B_warp + nh * (16 * ROWB) + ks * 32);
            #pragma unroll
            for (int mf = 0; mf < 4; mf++)
                #pragma unroll
                for (int nf = 0; nf < 4; nf++)
                    mma_fp8(acc[mf][nf], a[mf], b[nf >> 1][(nf & 1) * 2],
                            b[nf >> 1][(nf & 1) * 2 + 1]);
        }

        if (jt != bi) {
            #pragma unroll
            for (int mf = 0; mf < 4; mf++)
                #pragma unroll
                for (int nf = 0; nf < 4; nf++)
                    #pragma unroll
                    for (int q = 0; q < 4; q++)
                        rs[mf * 2 + (q >> 1)] += ex2(fmaf(acc[mf][nf][q], C1, -C1));
        } else {
            #pragma unroll
            for (int mf = 0; mf < 4; mf++)
                #pragma unroll
                for (int nf = 0; nf < 4; nf++)
                    #pragma unroll
                    for (int q = 0; q < 4; q++) {
                        int r = wm * 64 + mf * 16 + (l >> 2) + (q >> 1) * 8;
                        int c = wn * 32 + nf * 8 + 2 * (l & 3) + (q & 1);
                        float e = (r == c) ? 0.f
                                : ex2(fmaf(acc[mf][nf][q], C1, -C1));
                        rs[mf * 2 + (q >> 1)] += e;
                    }
        }
    }

    // Reduce across the 4 lanes sharing a row, then across warp_n via SMEM
    #pragma unroll
    for (int u = 0; u < 8; u++) {
        rs[u] += __shfl_xor_sync(0xffffffffu, rs[u], 1);
        rs[u] += __shfl_xor_sync(0xffffffffu, rs[u], 2);
    }
    __syncthreads();
    if ((l & 3) == 0) {
        #pragma unroll
        for (int u = 0; u < 8; u++) {
            int r = wm * 64 + (u >> 1) * 16 + (l >> 2) + 8 * (u & 1);
            Rbuf[wn * 128 + r] = rs[u];
        }
    }
    __syncthreads();
    if (tid < 128) {
        float tot = (Rbuf[tid] + Rbuf[128 + tid]) + (Rbuf[256 + tid] + Rbuf[384 + tid]);
        Rbuf[tid] = 2.f + logf(tot) - g_pos[bi * 128 + tid];
    }
    __syncthreads();
    if (tid == 0) {
        float acc = 0.f;
        #pragma unroll 8
        for (int i = 0; i < 128; i++) acc += Rbuf[i];
        g_partials[bi] = acc;
    }
}

__global__ void final_kernel(float* __restrict__ out) {
    if (threadIdx.x == 0) {
        float acc = 0.f;
        for (int i = 0; i < NTILES; i++) acc += g_partials[i];
        *out = acc / (float)N2;
    }
}

extern "C" void kernel_launch(void* const* d_in, const int* in_sizes, int n_in,
                              void* d_out, int out_size) {
    const float* z = (const float*)d_in[0];
    float* out = (float*)d_out;

    cudaFuncSetAttribute(ntxent_fp8_kernel,
                         cudaFuncAttributeMaxDynamicSharedMemorySize, SMEM_BYTES);

    convert_fp8_kernel<<<(N2 * DIM / 8) / 256, 256>>>(z);
    pos_kernel<<<N2 * 32 / 256, 256>>>(z);
    ntxent_fp8_kernel<<<NTILES, 256, SMEM_BYTES>>>();
    final_kernel<<<1, 32>>>(out);
}

// round 8
// speedup vs baseline: 1.0058x; 1.0058x over previous
#include <cuda_runtime.h>
#include <cuda_bf16.h>
#include <cstdint>
#include <math.h>

// NT-Xent loss: bf16 mma.sync, 512-thread persistent CTAs (4 warps/SMSP),
// static mixed-size work split over all 152 SMs.
// sim = 2*(z z^T); loss_i = -pos_exact_i + 2 + log(sum_{j!=i} exp(sim_ij - 2)).

#define N2 16384
#define DIM 128
#define NTILES 128
#define GRID_MAIN 152
#define NBIG 104                 // 104 blocks x 128 rows + 48 blocks x 64 rows = 16384
#define ROWB 272
#define A_OFF 0
#define B0_OFF 34816
#define B1_OFF 69632
#define RBUF_OFF 104448          // 4*128 floats
#define SMEM_BYTES 106496

__device__ __nv_bfloat16 g_zbf[N2 * DIM];
__device__ float g_pos[N2];
__device__ float g_partials[GRID_MAIN];

__device__ __forceinline__ uint32_t smem_u32(const void* p) {
    uint32_t a;
    asm("{ .reg .u64 t; cvta.to.shared.u64 t, %1; cvt.u32.u64 %0, t; }" : "=r"(a) : "l"(p));
    return a;
}
__device__ __forceinline__ void cp16(uint32_t dst, const void* src) {
    asm volatile("cp.async.cg.shared.global [%0], [%1], 16;" :: "r"(dst), "l"(src));
}
__device__ __forceinline__ void ldm_x4(uint32_t (&r)[4], uint32_t addr) {
    asm volatile("ldmatrix.sync.aligned.m8n8.x4.shared.b16 {%0,%1,%2,%3}, [%4];"
                 : "=r"(r[0]), "=r"(r[1]), "=r"(r[2]), "=r"(r[3]) : "r"(addr));
}
__device__ __forceinline__ void mma16816(float (&c)[4], const uint32_t (&a)[4],
                                         uint32_t b0, uint32_t b1) {
    asm volatile("mma.sync.aligned.m16n8k16.row.col.f32.bf16.bf16.f32 "
                 "{%0,%1,%2,%3},{%4,%5,%6,%7},{%8,%9},{%0,%1,%2,%3};"
                 : "+f"(c[0]), "+f"(c[1]), "+f"(c[2]), "+f"(c[3])
                 : "r"(a[0]), "r"(a[1]), "r"(a[2]), "r"(a[3]), "r"(b0), "r"(b1));
}
__device__ __forceinline__ float ex2(float x) {
    float y; asm("ex2.approx.f32 %0, %1;" : "=f"(y) : "f"(x)); return y;
}
#define C1 2.885390081777927f    // 2*log2(e)

__global__ void __launch_bounds__(256) convert_kernel(const float* __restrict__ z) {
    int i = blockIdx.x * blockDim.x + threadIdx.x;
    const float4 v = ((const float4*)z)[i];
    __nv_bfloat162 lo = __floats2bfloat162_rn(v.x, v.y);
    __nv_bfloat162 hi = __floats2bfloat162_rn(v.z, v.w);
    uint2 o;
    o.x = *(const uint32_t*)&lo;
    o.y = *(const uint32_t*)&hi;
    ((uint2*)g_zbf)[i] = o;
}

__global__ void __launch_bounds__(256) pos_kernel(const float* __restrict__ z) {
    int row = (blockIdx.x * 256 + threadIdx.x) >> 5;
    int l = threadIdx.x & 31;
    float4 a = ((const float4*)(z + (size_t)row * DIM))[l];
    float4 b = ((const float4*)(z + (size_t)(row ^ 8192) * DIM))[l];
    float d = fmaf(a.x, b.x, fmaf(a.y, b.y, fmaf(a.z, b.z, a.w * b.w)));
    #pragma unroll
    for (int off = 16; off >= 1; off >>= 1)
        d += __shfl_xor_sync(0xffffffffu, d, off);
    if (l == 0) g_pos[row] = 2.f * d;
}

// rows16 = number of 16-byte rows*16 chunks: tile of R rows has R*16 chunks.
__device__ __forceinline__ void prefetch_rows(uint32_t smbase, const char* gsrc,
                                              int tid, int nchunks) {
    for (int c = tid; c < nchunks; c += 512) {
        int r = c >> 4, kc = c & 15;
        cp16(smbase + r * ROWB + kc * 16, gsrc + r * 256 + kc * 16);
    }
}

// MF = 2: 128-row item; MF = 1: 64-row item. Warp grid 4(m) x 4(n).
template <int MF>
__device__ __forceinline__ void process_item(uint32_t s, float* Rbuf,
                                             int row_base, int item) {
    const int tid = threadIdx.x;
    const int w = tid >> 5, l = tid & 31;
    const int wm = w >> 2, wn = w & 3;
    const int ROWS = MF * 64;

    const char* zbf = (const char*)g_zbf;
    prefetch_rows(s + A_OFF, zbf + (size_t)row_base * 256, tid, ROWS * 16);
    prefetch_rows(s + B0_OFF, zbf, tid, 2048);
    asm volatile("cp.async.commit_group;" ::: "memory");

    const uint32_t laneA = (uint32_t)((l & 15) * ROWB + (l >> 4) * 16);
    const uint32_t laneB = (uint32_t)(((l & 7) + ((l >> 4) << 3)) * ROWB + (((l >> 3) & 1) << 4));
    const uint32_t A_warp = s + A_OFF + (uint32_t)wm * (MF * 16) * ROWB + laneA;

    const int dt = row_base >> 7;             // diag col-tile
    const int doff = row_base - dt * 128;     // 0 or 64

    float rs[MF * 2];
    #pragma unroll
    for (int u = 0; u < MF * 2; u++) rs[u] = 0.f;

    for (int jt = 0; jt < NTILES; jt++) {
        __syncthreads();
        if (jt + 1 < NTILES)
            prefetch_rows(s + ((jt & 1) ? B0_OFF : B1_OFF),
                          zbf + (size_t)(jt + 1) * 32768, tid, 2048);
        asm volatile("cp.async.commit_group;" ::: "memory");
        asm volatile("cp.async.wait_group 1;" ::: "memory");
        __syncthreads();

        const uint32_t B_warp = s + ((jt & 1) ? B1_OFF : B0_OFF)
                                  + (uint32_t)wn * 32 * ROWB + laneB;

        float acc[MF][4][4];
        #pragma unroll
        for (int mf = 0; mf < MF; mf++)
            #pragma unroll
            for (int nf = 0; nf < 4; nf++)
                #pragma unroll
                for (int q = 0; q < 4; q++) acc[mf][nf][q] = 0.f;

        #pragma unroll
        for (int ks = 0; ks < 8; ks++) {
            uint32_t a[MF][4], b[2][4];
            #pragma unroll
            for (int mf = 0; mf < MF; mf++)
                ldm_x4(a[mf], A_warp + mf * (16 * ROWB) + ks * 32);
            #pragma unroll
            for (int nh = 0; nh < 2; nh++)
                ldm_x4(b[nh], B_warp + nh * (16 * ROWB) + ks * 32);
            #pragma unroll
            for (int mf = 0; mf < MF; mf++)
                #pragma unroll
                for (int nf = 0; nf < 4; nf++)
                    mma16816(acc[mf][nf], a[mf], b[nf >> 1][(nf & 1) * 2],
                             b[nf >> 1][(nf & 1) * 2 + 1]);
        }

        if (jt != dt) {
            #pragma unroll
            for (int mf = 0; mf < MF; mf++)
                #pragma unroll
                for (int nf = 0; nf < 4; nf++)
                    #pragma unroll
                    for (int q = 0; q < 4; q++)
                        rs[mf * 2 + (q >> 1)] += ex2(fmaf(acc[mf][nf][q], C1, -C1));
        } else {
            #pragma unroll
            for (int mf = 0; mf < MF; mf++)
                #pragma unroll
                for (int nf = 0; nf < 4; nf++)
                    #pragma unroll
                    for (int q = 0; q < 4; q++) {
                        int r = wm * (MF * 16) + mf * 16 + (l >> 2) + (q >> 1) * 8;
                        int c = wn * 32 + nf * 8 + 2 * (l & 3) + (q & 1);
                        float e = (c == r + doff) ? 0.f
                                : ex2(fmaf(acc[mf][nf][q], C1, -C1));
                        rs[mf * 2 + (q >> 1)] += e;
                    }
        }
    }

    // reduce over the 4 lanes sharing a row, then over the 4 n-warps
    #pragma unroll
    for (int u = 0; u < MF * 2; u++) {
        rs[u] += __shfl_xor_sync(0xffffffffu, rs[u], 1);
        rs[u] += __shfl_xor_sync(0xffffffffu, rs[u], 2);
    }
    __syncthreads();
    if ((l & 3) == 0) {
        #pragma unroll
        for (int u = 0; u < MF * 2; u++) {
            int r = wm * (MF * 16) + (u >> 1) * 16 + (l >> 2) + 8 * (u & 1);
            Rbuf[wn * 128 + r] = rs[u];
        }
    }
    __syncthreads();
    if (tid < ROWS) {
        float tot = (Rbuf[tid] + Rbuf[128 + tid]) + (Rbuf[256 + tid] + Rbuf[384 + tid]);
        Rbuf[tid] = 2.f + logf(tot) - g_pos[row_base + tid];
    }
    __syncthreads();
    if (tid == 0) {
        float acc = 0.f;
        #pragma unroll 8
        for (int i = 0; i < ROWS; i++) acc += Rbuf[i];
        g_partials[item] = acc;
    }
}

__global__ void __launch_bounds__(512, 1) ntxent_main_kernel() {
    extern __shared__ char sm[];
    const uint32_t s = smem_u32(sm);
    float* Rbuf = (float*)(sm + RBUF_OFF);
    const int bi = blockIdx.x;
    if (bi < NBIG) {
        process_item<2>(s, Rbuf, bi * 128, bi);
    } else {
        process_item<1>(s, Rbuf, NBIG * 128 + (bi - NBIG) * 64, bi);
    }
}

__global__ void final_kernel(float* __restrict__ out) {
    if (threadIdx.x == 0) {
        float acc = 0.f;
        for (int i = 0; i < GRID_MAIN; i++) acc += g_partials[i];
        *out = acc / (float)N2;
    }
}

extern "C" void kernel_launch(void* const* d_in, const int* in_sizes, int n_in,
                              void* d_out, int out_size) {
    const float* z = (const float*)d_in[0];
    float* out = (float*)d_out;

    cudaFuncSetAttribute(ntxent_main_kernel,
                         cudaFuncAttributeMaxDynamicSharedMemorySize, SMEM_BYTES);

    convert_kernel<<<(N2 * DIM / 4) / 256, 256>>>(z);
    pos_kernel<<<N2 * 32 / 256, 256>>>(z);
    ntxent_main_kernel<<<GRID_MAIN, 512, SMEM_BYTES>>>();
    final_kernel<<<1, 32>>>(out);
}

// round 9
// speedup vs baseline: 1.1553x; 1.1486x over previous
#include <cuda_runtime.h>
#include <cuda_bf16.h>
#include <cstdint>
#include <math.h>

// NT-Xent loss: bf16 mma.sync with A fragments register-resident across the
// whole column sweep (A tile is loop-invariant). 128 CTAs x 256 threads.
// sim = 2*(z z^T); loss_i = -pos_exact_i + 2 + log(sum_{j!=i} exp(sim_ij - 2)).

#define N2 16384
#define DIM 128
#define NTILES 128
#define ROWB 272                  // padded SMEM row bytes
#define A_OFF 0
#define B0_OFF 34816
#define B1_OFF 69632
#define RBUF_OFF 104448           // 4*128 floats
#define SMEM_BYTES 106496

__device__ __nv_bfloat16 g_zbf[N2 * DIM];
__device__ float g_pos[N2];
__device__ float g_partials[NTILES];

__device__ __forceinline__ uint32_t smem_u32(const void* p) {
    uint32_t a;
    asm("{ .reg .u64 t; cvta.to.shared.u64 t, %1; cvt.u32.u64 %0, t; }" : "=r"(a) : "l"(p));
    return a;
}
__device__ __forceinline__ void cp16(uint32_t dst, const void* src) {
    asm volatile("cp.async.cg.shared.global [%0], [%1], 16;" :: "r"(dst), "l"(src));
}
__device__ __forceinline__ void ldm_x4(uint32_t (&r)[4], uint32_t addr) {
    asm volatile("ldmatrix.sync.aligned.m8n8.x4.shared.b16 {%0,%1,%2,%3}, [%4];"
                 : "=r"(r[0]), "=r"(r[1]), "=r"(r[2]), "=r"(r[3]) : "r"(addr));
}
__device__ __forceinline__ void mma16816(float (&c)[4], const uint32_t* a,
                                         uint32_t b0, uint32_t b1) {
    asm volatile("mma.sync.aligned.m16n8k16.row.col.f32.bf16.bf16.f32 "
                 "{%0,%1,%2,%3},{%4,%5,%6,%7},{%8,%9},{%0,%1,%2,%3};"
                 : "+f"(c[0]), "+f"(c[1]), "+f"(c[2]), "+f"(c[3])
                 : "r"(a[0]), "r"(a[1]), "r"(a[2]), "r"(a[3]), "r"(b0), "r"(b1));
}
__device__ __forceinline__ float ex2(float x) {
    float y; asm("ex2.approx.f32 %0, %1;" : "=f"(y) : "f"(x)); return y;
}
#define C1 2.885390081777927f     // 2*log2(e)

__global__ void __launch_bounds__(256) convert_kernel(const float* __restrict__ z) {
    int i = blockIdx.x * blockDim.x + threadIdx.x;
    const float4 v = ((const float4*)z)[i];
    __nv_bfloat162 lo = __floats2bfloat162_rn(v.x, v.y);
    __nv_bfloat162 hi = __floats2bfloat162_rn(v.z, v.w);
    uint2 o;
    o.x = *(const uint32_t*)&lo;
    o.y = *(const uint32_t*)&hi;
    ((uint2*)g_zbf)[i] = o;
}

__global__ void __launch_bounds__(256) pos_kernel(const float* __restrict__ z) {
    int row = (blockIdx.x * 256 + threadIdx.x) >> 5;
    int l = threadIdx.x & 31;
    float4 a = ((const float4*)(z + (size_t)row * DIM))[l];
    float4 b = ((const float4*)(z + (size_t)(row ^ 8192) * DIM))[l];
    float d = fmaf(a.x, b.x, fmaf(a.y, b.y, fmaf(a.z, b.z, a.w * b.w)));
    #pragma unroll
    for (int off = 16; off >= 1; off >>= 1)
        d += __shfl_xor_sync(0xffffffffu, d, off);
    if (l == 0) g_pos[row] = 2.f * d;
}

__device__ __forceinline__ void prefetch_tile(uint32_t smbase, const char* gsrc, int tid) {
    #pragma unroll
    for (int i = 0; i < 8; i++) {
        int c = tid + i * 256;
        int r = c >> 4, kc = c & 15;
        cp16(smbase + r * ROWB + kc * 16, gsrc + r * 256 + kc * 16);
    }
}

__global__ void __launch_bounds__(256, 1) ntxent_areg_kernel() {
    extern __shared__ char sm[];
    const uint32_t s = smem_u32(sm);
    float* Rbuf = (float*)(sm + RBUF_OFF);

    const int bi = blockIdx.x;
    const int tid = threadIdx.x;
    const int w = tid >> 5, l = tid & 31;
    const int wm = w >> 2, wn = w & 3;        // 2 (m) x 4 (n) warps

    const char* zbf = (const char*)g_zbf;

    // Load A tile + B tile 0
    prefetch_tile(s + A_OFF, zbf + (size_t)bi * 32768, tid);
    prefetch_tile(s + B0_OFF, zbf, tid);
    asm volatile("cp.async.commit_group;" ::: "memory");
    asm volatile("cp.async.wait_group 0;" ::: "memory");
    __syncthreads();

    const uint32_t laneA = (uint32_t)((l & 15) * ROWB + (l >> 4) * 16);
    const uint32_t laneB = (uint32_t)(((l & 7) + ((l >> 4) << 3)) * ROWB + (((l >> 3) & 1) << 4));
    const uint32_t A_warp = s + A_OFF + (uint32_t)wm * 64 * ROWB + laneA;

    // ---- Hoist ALL A fragments into registers (loop-invariant) ----
    uint32_t afr[4][8][4];
    #pragma unroll
    for (int mf = 0; mf < 4; mf++)
        #pragma unroll
        for (int ks = 0; ks < 8; ks++)
            ldm_x4(afr[mf][ks], A_warp + mf * (16 * ROWB) + ks * 32);

    float rs[8];
    #pragma unroll
    for (int u = 0; u < 8; u++) rs[u] = 0.f;

    for (int jt = 0; jt < NTILES; jt++) {
        __syncthreads();
        if (jt + 1 < NTILES)
            prefetch_tile(s + ((jt & 1) ? B0_OFF : B1_OFF),
                          zbf + (size_t)(jt + 1) * 32768, tid);
        asm volatile("cp.async.commit_group;" ::: "memory");
        asm volatile("cp.async.wait_group 1;" ::: "memory");
        __syncthreads();

        const uint32_t B_warp = s + ((jt & 1) ? B1_OFF : B0_OFF)
                                  + (uint32_t)wn * 32 * ROWB + laneB;

        float acc[4][4][4];
        #pragma unroll
        for (int mf = 0; mf < 4; mf++)
            #pragma unroll
            for (int nf = 0; nf < 4; nf++)
                #pragma unroll
                for (int q = 0; q < 4; q++) acc[mf][nf][q] = 0.f;

        #pragma unroll
        for (int ks = 0; ks < 8; ks++) {
            uint32_t b[2][4];
            #pragma unroll
            for (int nh = 0; nh < 2; nh++)
                ldm_x4(b[nh], B_warp + nh * (16 * ROWB) + ks * 32);
            #pragma unroll
            for (int mf = 0; mf < 4; mf++)
                #pragma unroll
                for (int nf = 0; nf < 4; nf++)
                    mma16816(acc[mf][nf], afr[mf][ks], b[nf >> 1][(nf & 1) * 2],
                             b[nf >> 1][(nf & 1) * 2 + 1]);
        }

        if (jt != bi) {
            #pragma unroll
            for (int mf = 0; mf < 4; mf++)
                #pragma unroll
                for (int nf = 0; nf < 4; nf++)
                    #pragma unroll
                    for (int q = 0; q < 4; q++)
                        rs[mf * 2 + (q >> 1)] += ex2(fmaf(acc[mf][nf][q], C1, -C1));
        } else {
            #pragma unroll
            for (int mf = 0; mf < 4; mf++)
                #pragma unroll
                for (int nf = 0; nf < 4; nf++)
                    #pragma unroll
                    for (int q = 0; q < 4; q++) {
                        int r = wm * 64 + mf * 16 + (l >> 2) + (q >> 1) * 8;
                        int c = wn * 32 + nf * 8 + 2 * (l & 3) + (q & 1);
                        float e = (r == c) ? 0.f
                                : ex2(fmaf(acc[mf][nf][q], C1, -C1));
                        rs[mf * 2 + (q >> 1)] += e;
                    }
        }
    }

    #pragma unroll
    for (int u = 0; u < 8; u++) {
        rs[u] += __shfl_xor_sync(0xffffffffu, rs[u], 1);
        rs[u] += __shfl_xor_sync(0xffffffffu, rs[u], 2);
    }
    __syncthreads();
    if ((l & 3) == 0) {
        #pragma unroll
        for (int u = 0; u < 8; u++) {
            int r = wm * 64 + (u >> 1) * 16 + (l >> 2) + 8 * (u & 1);
            Rbuf[wn * 128 + r] = rs[u];
        }
    }
    __syncthreads();
    if (tid < 128) {
        float tot = (Rbuf[tid] + Rbuf[128 + tid]) + (Rbuf[256 + tid] + Rbuf[384 + tid]);
        Rbuf[tid] = 2.f + logf(tot) - g_pos[bi * 128 + tid];
    }
    __syncthreads();
    if (tid == 0) {
        float acc = 0.f;
        #pragma unroll 8
        for (int i = 0; i < 128; i++) acc += Rbuf[i];
        g_partials[bi] = acc;
    }
}

__global__ void final_kernel(float* __restrict__ out) {
    if (threadIdx.x == 0) {
        float acc = 0.f;
        for (int i = 0; i < NTILES; i++) acc += g_partials[i];
        *out = acc / (float)N2;
    }
}

extern "C" void kernel_launch(void* const* d_in, const int* in_sizes, int n_in,
                              void* d_out, int out_size) {
    const float* z = (const float*)d_in[0];
    float* out = (float*)d_out;

    cudaFuncSetAttribute(ntxent_areg_kernel,
                         cudaFuncAttributeMaxDynamicSharedMemorySize, SMEM_BYTES);

    convert_kernel<<<(N2 * DIM / 4) / 256, 256>>>(z);
    pos_kernel<<<N2 * 32 / 256, 256>>>(z);
    ntxent_areg_kernel<<<NTILES, 256, SMEM_BYTES>>>();
    final_kernel<<<1, 32>>>(out);
}

// round 10
// speedup vs baseline: 1.8040x; 1.5615x over previous
#include <cuda_runtime.h>
#include <cuda_bf16.h>
#include <cstdint>
#include <math.h>

// NT-Xent loss, symmetric tournament schedule.
// CTA rb sweeps jt = rb..rb+64 (mod 128) [rb<64] or rb..rb+63 [rb>=64]:
// every unordered block pair covered exactly once. Row-sums accumulate in
// registers over the whole sweep (R4 structure); column-sums are flushed per
// pair with warp-local shuffles + STG (no extra block barrier).

#define N2 16384
#define DIM 128
#define ROWB 272
#define A_OFF 0
#define B0_OFF 34816
#define B1_OFF 69632
#define RBUF_OFF 104448           // 4*128 floats
#define SMEM_BYTES 106496

__device__ __nv_bfloat16 g_zbf[N2 * DIM];
__device__ float g_pos[N2];
__device__ float g_gr[N2];                     // direct row sums per row
__device__ float g_csp[128 * 64 * 2 * 128];    // 8 MB: [rb][d-1][wm][col]
__device__ float g_partials[128];

__device__ __forceinline__ uint32_t smem_u32(const void* p) {
    uint32_t a;
    asm("{ .reg .u64 t; cvta.to.shared.u64 t, %1; cvt.u32.u64 %0, t; }" : "=r"(a) : "l"(p));
    return a;
}
__device__ __forceinline__ void cp16(uint32_t dst, const void* src) {
    asm volatile("cp.async.cg.shared.global [%0], [%1], 16;" :: "r"(dst), "l"(src));
}
__device__ __forceinline__ void ldm_x4(uint32_t (&r)[4], uint32_t addr) {
    asm volatile("ldmatrix.sync.aligned.m8n8.x4.shared.b16 {%0,%1,%2,%3}, [%4];"
                 : "=r"(r[0]), "=r"(r[1]), "=r"(r[2]), "=r"(r[3]) : "r"(addr));
}
__device__ __forceinline__ void mma16816(float (&c)[4], const uint32_t (&a)[4],
                                         uint32_t b0, uint32_t b1) {
    asm volatile("mma.sync.aligned.m16n8k16.row.col.f32.bf16.bf16.f32 "
                 "{%0,%1,%2,%3},{%4,%5,%6,%7},{%8,%9},{%0,%1,%2,%3};"
                 : "+f"(c[0]), "+f"(c[1]), "+f"(c[2]), "+f"(c[3])
                 : "r"(a[0]), "r"(a[1]), "r"(a[2]), "r"(a[3]), "r"(b0), "r"(b1));
}
__device__ __forceinline__ float ex2(float x) {
    float y; asm("ex2.approx.f32 %0, %1;" : "=f"(y) : "f"(x)); return y;
}
#define C1 2.885390081777927f     // 2*log2(e)

__global__ void __launch_bounds__(256) convert_kernel(const float* __restrict__ z) {
    int i = blockIdx.x * blockDim.x + threadIdx.x;
    const float4 v = ((const float4*)z)[i];
    __nv_bfloat162 lo = __floats2bfloat162_rn(v.x, v.y);
    __nv_bfloat162 hi = __floats2bfloat162_rn(v.z, v.w);
    uint2 o;
    o.x = *(const uint32_t*)&lo;
    o.y = *(const uint32_t*)&hi;
    ((uint2*)g_zbf)[i] = o;
}

__global__ void __launch_bounds__(256) pos_kernel(const float* __restrict__ z) {
    int row = (blockIdx.x * 256 + threadIdx.x) >> 5;
    int l = threadIdx.x & 31;
    float4 a = ((const float4*)(z + (size_t)row * DIM))[l];
    float4 b = ((const float4*)(z + (size_t)(row ^ 8192) * DIM))[l];
    float d = fmaf(a.x, b.x, fmaf(a.y, b.y, fmaf(a.z, b.z, a.w * b.w)));
    #pragma unroll
    for (int off = 16; off >= 1; off >>= 1)
        d += __shfl_xor_sync(0xffffffffu, d, off);
    if (l == 0) g_pos[row] = 2.f * d;
}

__device__ __forceinline__ void prefetch_tile(uint32_t smbase, const char* gsrc, int tid) {
    #pragma unroll
    for (int i = 0; i < 8; i++) {
        int c = tid + i * 256;
        int r = c >> 4, kc = c & 15;
        cp16(smbase + r * ROWB + kc * 16, gsrc + r * 256 + kc * 16);
    }
}

__global__ void __launch_bounds__(256, 1) ntxent_sym2_kernel() {
    extern __shared__ char sm[];
    const uint32_t s = smem_u32(sm);
    float* Rbuf = (float*)(sm + RBUF_OFF);

    const int rb = blockIdx.x;
    const int tid = threadIdx.x;
    const int w = tid >> 5, l = tid & 31;
    const int wm = w >> 2, wn = w & 3;        // 2 (m) x 4 (n)
    const int NU = (rb < 64) ? 65 : 64;       // diag + 64 or 63 pairs

    const char* zbf = (const char*)g_zbf;

    prefetch_tile(s + A_OFF, zbf + (size_t)rb * 32768, tid);
    prefetch_tile(s + B0_OFF, zbf + (size_t)rb * 32768, tid);  // unit 0 = diag
    asm volatile("cp.async.commit_group;" ::: "memory");

    const uint32_t laneA = (uint32_t)((l & 15) * ROWB + (l >> 4) * 16);
    const uint32_t laneB = (uint32_t)(((l & 7) + ((l >> 4) << 3)) * ROWB + (((l >> 3) & 1) << 4));
    const uint32_t A_warp = s + A_OFF + (uint32_t)wm * 64 * ROWB + laneA;

    float rs[8];
    #pragma unroll
    for (int u = 0; u < 8; u++) rs[u] = 0.f;

    for (int u = 0; u < NU; u++) {
        __syncthreads();
        if (u + 1 < NU) {
            int jn = (rb + u + 1) & 127;
            prefetch_tile(s + ((u & 1) ? B0_OFF : B1_OFF), zbf + (size_t)jn * 32768, tid);
        }
        asm volatile("cp.async.commit_group;" ::: "memory");
        asm volatile("cp.async.wait_group 1;" ::: "memory");
        __syncthreads();

        const uint32_t B_warp = s + ((u & 1) ? B1_OFF : B0_OFF)
                                  + (uint32_t)wn * 32 * ROWB + laneB;

        float acc[4][4][4];
        #pragma unroll
        for (int mf = 0; mf < 4; mf++)
            #pragma unroll
            for (int nf = 0; nf < 4; nf++)
                #pragma unroll
                for (int q = 0; q < 4; q++) acc[mf][nf][q] = 0.f;

        #pragma unroll
        for (int ks = 0; ks < 8; ks++) {
            uint32_t a[4][4], b[2][4];
            #pragma unroll
            for (int mf = 0; mf < 4; mf++)
                ldm_x4(a[mf], A_warp + mf * (16 * ROWB) + ks * 32);
            #pragma unroll
            for (int nh = 0; nh < 2; nh++)
                ldm_x4(b[nh], B_warp + nh * (16 * ROWB) + ks * 32);
            #pragma unroll
            for (int mf = 0; mf < 4; mf++)
                #pragma unroll
                for (int nf = 0; nf < 4; nf++)
                    mma16816(acc[mf][nf], a[mf], b[nf >> 1][(nf & 1) * 2],
                             b[nf >> 1][(nf & 1) * 2 + 1]);
        }

        if (u == 0) {
            // diag tile: skip r==c, rows only (no column flush)
            #pragma unroll
            for (int mf = 0; mf < 4; mf++)
                #pragma unroll
                for (int nf = 0; nf < 4; nf++)
                    #pragma unroll
                    for (int q = 0; q < 4; q++) {
                        int r = wm * 64 + mf * 16 + (l >> 2) + (q >> 1) * 8;
                        int c = wn * 32 + nf * 8 + 2 * (l & 3) + (q & 1);
                        float e = (r == c) ? 0.f
                                : ex2(fmaf(acc[mf][nf][q], C1, -C1));
                        rs[mf * 2 + (q >> 1)] += e;
                    }
        } else {
            float cs[8];
            #pragma unroll
            for (int v = 0; v < 8; v++) cs[v] = 0.f;
            #pragma unroll
            for (int mf = 0; mf < 4; mf++)
                #pragma unroll
                for (int nf = 0; nf < 4; nf++)
                    #pragma unroll
                    for (int q = 0; q < 4; q++) {
                        float e = ex2(fmaf(acc[mf][nf][q], C1, -C1));
                        rs[mf * 2 + (q >> 1)] += e;
                        cs[nf * 2 + (q & 1)] += e;
                    }
            // warp-local column reduce over the 8 lane-rows (l>>2)
            #pragma unroll
            for (int v = 0; v < 8; v++) {
                cs[v] += __shfl_xor_sync(0xffffffffu, cs[v], 4);
                cs[v] += __shfl_xor_sync(0xffffffffu, cs[v], 8);
                cs[v] += __shfl_xor_sync(0xffffffffu, cs[v], 16);
            }
            if (l < 4) {
                float* dst = g_csp + (((size_t)rb * 64 + (u - 1)) * 2 + wm) * 128;
                #pragma unroll
                for (int v = 0; v < 8; v++) {
                    int c = wn * 32 + (v >> 1) * 8 + 2 * l + (v & 1);
                    dst[c] = cs[v];
                }
            }
        }
    }

    // final row reduction (once per CTA)
    #pragma unroll
    for (int u = 0; u < 8; u++) {
        rs[u] += __shfl_xor_sync(0xffffffffu, rs[u], 1);
        rs[u] += __shfl_xor_sync(0xffffffffu, rs[u], 2);
    }
    __syncthreads();
    if ((l & 3) == 0) {
        #pragma unroll
        for (int u = 0; u < 8; u++) {
            int r = wm * 64 + (u >> 1) * 16 + (l >> 2) + 8 * (u & 1);
            Rbuf[wn * 128 + r] = rs[u];
        }
    }
    __syncthreads();
    if (tid < 128) {
        g_gr[rb * 128 + tid] = (Rbuf[tid] + Rbuf[128 + tid])
                             + (Rbuf[256 + tid] + Rbuf[384 + tid]);
    }
}

// block j: total row sums = own rs + cs contributions from pairs (rb, d) with
// (j - rb) mod 128 == d, valid iff d <= 63 or rb < 64. Fixed order = deterministic.
__global__ void __launch_bounds__(128) combine_kernel() {
    const int j = blockIdx.x;
    const int r = threadIdx.x;
    float sum = g_gr[j * 128 + r];
    for (int d = 1; d <= 64; d++) {
        int rb = (j - d) & 127;
        if (d <= 63 || rb < 64) {
            const float* p = g_csp + (((size_t)rb * 64 + (d - 1)) * 2) * 128;
            sum += p[r] + p[128 + r];
        }
    }
    float loss = 2.f + logf(sum) - g_pos[j * 128 + r];
    __shared__ float red[128];
    red[r] = loss;
    __syncthreads();
    if (r == 0) {
        float acc = 0.f;
        #pragma unroll 8
        for (int i = 0; i < 128; i++) acc += red[i];
        g_partials[j] = acc;
    }
}

__global__ void final_kernel(float* __restrict__ out) {
    if (threadIdx.x == 0) {
        float acc = 0.f;
        for (int i = 0; i < 128; i++) acc += g_partials[i];
        *out = acc / (float)N2;
    }
}

extern "C" void kernel_launch(void* const* d_in, const int* in_sizes, int n_in,
                              void* d_out, int out_size) {
    const float* z = (const float*)d_in[0];
    float* out = (float*)d_out;

    cudaFuncSetAttribute(ntxent_sym2_kernel,
                         cudaFuncAttributeMaxDynamicSharedMemorySize, SMEM_BYTES);

    convert_kernel<<<(N2 * DIM / 4) / 256, 256>>>(z);
    pos_kernel<<<N2 * 32 / 256, 256>>>(z);
    ntxent_sym2_kernel<<<128, 256, SMEM_BYTES>>>();
    combine_kernel<<<128, 128>>>();
    final_kernel<<<1, 32>>>(out);
}

// round 11
// speedup vs baseline: 1.9410x; 1.0759x over previous
#include <cuda_runtime.h>
#include <cuda_bf16.h>
#include <cstdint>
#include <math.h>

// NT-Xent loss, balanced tournament schedule over 152 CTAs, 3 launches.
// Unit list (rb-major): rb<64 -> 65 units (diag + d=1..64), rb>=64 -> 64 units
// (diag + d=1..63); every unordered block pair covered exactly once.
// Row sums live in registers per rb-run (<=2 runs/CTA); column sums flushed
// per unit with warp shuffles + STG. Combine kernel assembles, computes loss,
// and the last block writes the mean (atomic-counter pattern, fixed-order sum).

#define N2 16384
#define DIM 128
#define NUNITS 8256
#define GRID_MAIN 152
#define ROWB 272
#define A_OFF 0
#define B0_OFF 34816
#define B1_OFF 69632
#define SMEM_BYTES 104448

__device__ __nv_bfloat16 g_zbf[N2 * DIM];
__device__ float g_pos[N2];
__device__ float g_rowpart[GRID_MAIN * 2 * 4 * 128];   // [cta][run][wn][row]
__device__ float g_csp[128 * 64 * 2 * 128];            // [rb][d-1][wm][col]
__device__ float g_partials[128];
__device__ int g_cnt = 0;

__device__ __forceinline__ uint32_t smem_u32(const void* p) {
    uint32_t a;
    asm("{ .reg .u64 t; cvta.to.shared.u64 t, %1; cvt.u32.u64 %0, t; }" : "=r"(a) : "l"(p));
    return a;
}
__device__ __forceinline__ void cp16(uint32_t dst, const void* src) {
    asm volatile("cp.async.cg.shared.global [%0], [%1], 16;" :: "r"(dst), "l"(src));
}
__device__ __forceinline__ void ldm_x4(uint32_t (&r)[4], uint32_t addr) {
    asm volatile("ldmatrix.sync.aligned.m8n8.x4.shared.b16 {%0,%1,%2,%3}, [%4];"
                 : "=r"(r[0]), "=r"(r[1]), "=r"(r[2]), "=r"(r[3]) : "r"(addr));
}
__device__ __forceinline__ void mma16816(float (&c)[4], const uint32_t (&a)[4],
                                         uint32_t b0, uint32_t b1) {
    asm volatile("mma.sync.aligned.m16n8k16.row.col.f32.bf16.bf16.f32 "
                 "{%0,%1,%2,%3},{%4,%5,%6,%7},{%8,%9},{%0,%1,%2,%3};"
                 : "+f"(c[0]), "+f"(c[1]), "+f"(c[2]), "+f"(c[3])
                 : "r"(a[0]), "r"(a[1]), "r"(a[2]), "r"(a[3]), "r"(b0), "r"(b1));
}
__device__ __forceinline__ float ex2(float x) {
    float y; asm("ex2.approx.f32 %0, %1;" : "=f"(y) : "f"(x)); return y;
}
#define C1 2.885390081777927f     // 2*log2(e)

// unit n -> (rb, u); jt = (rb+u) & 127, u=0 is the diag tile.
__device__ __forceinline__ void decode_unit(int n, int& rb, int& u) {
    if (n < 4160) { rb = n / 65; u = n - rb * 65; }
    else { int m = n - 4160; rb = 64 + (m >> 6); u = m & 63; }
}

// ---- prep: bf16 convert + exact f32 positives, fused ----
__global__ void __launch_bounds__(256) prep_kernel(const float* __restrict__ z) {
    if (blockIdx.x < 2048) {
        int i = blockIdx.x * 256 + threadIdx.x;
        const float4 v = ((const float4*)z)[i];
        __nv_bfloat162 lo = __floats2bfloat162_rn(v.x, v.y);
        __nv_bfloat162 hi = __floats2bfloat162_rn(v.z, v.w);
        uint2 o;
        o.x = *(const uint32_t*)&lo;
        o.y = *(const uint32_t*)&hi;
        ((uint2*)g_zbf)[i] = o;
    } else {
        int row = ((blockIdx.x - 2048) * 256 + threadIdx.x) >> 5;
        int l = threadIdx.x & 31;
        float4 a = ((const float4*)(z + (size_t)row * DIM))[l];
        float4 b = ((const float4*)(z + (size_t)(row ^ 8192) * DIM))[l];
        float d = fmaf(a.x, b.x, fmaf(a.y, b.y, fmaf(a.z, b.z, a.w * b.w)));
        #pragma unroll
        for (int off = 16; off >= 1; off >>= 1)
            d += __shfl_xor_sync(0xffffffffu, d, off);
        if (l == 0) g_pos[row] = 2.f * d;
    }
}

__device__ __forceinline__ void prefetch_tile(uint32_t smbase, const char* gsrc, int tid) {
    #pragma unroll
    for (int i = 0; i < 8; i++) {
        int c = tid + i * 256;
        int r = c >> 4, kc = c & 15;
        cp16(smbase + r * ROWB + kc * 16, gsrc + r * 256 + kc * 16);
    }
}

__device__ __forceinline__ void flush_rows(float (&rs)[8], int cta, int runidx,
                                           int wm, int wn, int l) {
    #pragma unroll
    for (int u = 0; u < 8; u++) {
        rs[u] += __shfl_xor_sync(0xffffffffu, rs[u], 1);
        rs[u] += __shfl_xor_sync(0xffffffffu, rs[u], 2);
    }
    if ((l & 3) == 0) {
        float* dst = g_rowpart + (((size_t)cta * 2 + runidx) * 4 + wn) * 128;
        #pragma unroll
        for (int u = 0; u < 8; u++) {
            int r = wm * 64 + (u >> 1) * 16 + (l >> 2) + 8 * (u & 1);
            dst[r] = rs[u];
        }
    }
    #pragma unroll
    for (int u = 0; u < 8; u++) rs[u] = 0.f;
}

__global__ void __launch_bounds__(256, 1) ntxent_tour_kernel() {
    extern __shared__ char sm[];
    const uint32_t s = smem_u32(sm);

    const int cta = blockIdx.x;
    const int tid = threadIdx.x;
    const int w = tid >> 5, l = tid & 31;
    const int wm = w >> 2, wn = w & 3;

    const int n0 = (cta * NUNITS) / GRID_MAIN;
    const int n1 = ((cta + 1) * NUNITS) / GRID_MAIN;

    const char* zbf = (const char*)g_zbf;
    const uint32_t laneA = (uint32_t)((l & 15) * ROWB + (l >> 4) * 16);
    const uint32_t laneB = (uint32_t)(((l & 7) + ((l >> 4) << 3)) * ROWB + (((l >> 3) & 1) << 4));
    const uint32_t A_warp = s + A_OFF + (uint32_t)wm * 64 * ROWB + laneA;

    // prologue: A(rb(n0)) + B(jt(n0)) -> buf0, full drain
    int cur_rb, u0;
    decode_unit(n0, cur_rb, u0);
    prefetch_tile(s + A_OFF, zbf + (size_t)cur_rb * 32768, tid);
    prefetch_tile(s + B0_OFF, zbf + (size_t)((cur_rb + u0) & 127) * 32768, tid);
    asm volatile("cp.async.commit_group;" ::: "memory");
    asm volatile("cp.async.wait_group 0;" ::: "memory");
    __syncthreads();

    float rs[8];
    #pragma unroll
    for (int u = 0; u < 8; u++) rs[u] = 0.f;
    int runidx = 0;
    int p = 0;

    for (int n = n0; n < n1; n++) {
        int rb, u;
        decode_unit(n, rb, u);
        const int jt = (rb + u) & 127;

        __syncthreads();                        // all reads of buf p^1 (2 iters ago) done
        bool newA = (rb != cur_rb);
        if (newA) {
            flush_rows(rs, cta, runidx, wm, wn, l);
            runidx = 1;
            cur_rb = rb;
            prefetch_tile(s + A_OFF, zbf + (size_t)rb * 32768, tid);
        }
        if (n + 1 < n1) {
            int rb2, u2;
            decode_unit(n + 1, rb2, u2);
            prefetch_tile(s + (p ? B0_OFF : B1_OFF),
                          zbf + (size_t)((rb2 + u2) & 127) * 32768, tid);
        }
        asm volatile("cp.async.commit_group;" ::: "memory");
        if (newA) asm volatile("cp.async.wait_group 0;" ::: "memory");
        else      asm volatile("cp.async.wait_group 1;" ::: "memory");
        __syncthreads();

        const uint32_t B_warp = s + (p ? B1_OFF : B0_OFF)
                                  + (uint32_t)wn * 32 * ROWB + laneB;

        float acc[4][4][4];
        #pragma unroll
        for (int mf = 0; mf < 4; mf++)
            #pragma unroll
            for (int nf = 0; nf < 4; nf++)
                #pragma unroll
                for (int q = 0; q < 4; q++) acc[mf][nf][q] = 0.f;

        #pragma unroll
        for (int ks = 0; ks < 8; ks++) {
            uint32_t a[4][4], b[2][4];
            #pragma unroll
            for (int mf = 0; mf < 4; mf++)
                ldm_x4(a[mf], A_warp + mf * (16 * ROWB) + ks * 32);
            #pragma unroll
            for (int nh = 0; nh < 2; nh++)
                ldm_x4(b[nh], B_warp + nh * (16 * ROWB) + ks * 32);
            #pragma unroll
            for (int mf = 0; mf < 4; mf++)
                #pragma unroll
                for (int nf = 0; nf < 4; nf++)
                    mma16816(acc[mf][nf], a[mf], b[nf >> 1][(nf & 1) * 2],
                             b[nf >> 1][(nf & 1) * 2 + 1]);
        }

        if (u == 0) {
            // diag tile: skip r==c, rows only
            #pragma unroll
            for (int mf = 0; mf < 4; mf++)
                #pragma unroll
                for (int nf = 0; nf < 4; nf++)
                    #pragma unroll
                    for (int q = 0; q < 4; q++) {
                        int r = wm * 64 + mf * 16 + (l >> 2) + (q >> 1) * 8;
                        int c = wn * 32 + nf * 8 + 2 * (l & 3) + (q & 1);
                        float e = (r == c) ? 0.f
                                : ex2(fmaf(acc[mf][nf][q], C1, -C1));
                        rs[mf * 2 + (q >> 1)] += e;
                    }
        } else {
            float cs[8];
            #pragma unroll
            for (int v = 0; v < 8; v++) cs[v] = 0.f;
            #pragma unroll
            for (int mf = 0; mf < 4; mf++)
                #pragma unroll
                for (int nf = 0; nf < 4; nf++)
                    #pragma unroll
                    for (int q = 0; q < 4; q++) {
                        float e = ex2(fmaf(acc[mf][nf][q], C1, -C1));
                        rs[mf * 2 + (q >> 1)] += e;
                        cs[nf * 2 + (q & 1)] += e;
                    }
            #pragma unroll
            for (int v = 0; v < 8; v++) {
                cs[v] += __shfl_xor_sync(0xffffffffu, cs[v], 4);
                cs[v] += __shfl_xor_sync(0xffffffffu, cs[v], 8);
                cs[v] += __shfl_xor_sync(0xffffffffu, cs[v], 16);
            }
            if (l < 4) {
                float* dst = g_csp + (((size_t)rb * 64 + (u - 1)) * 2 + wm) * 128;
                #pragma unroll
                for (int v = 0; v < 8; v++) {
                    int c = wn * 32 + (v >> 1) * 8 + 2 * l + (v & 1);
                    dst[c] = cs[v];
                }
            }
        }
        p ^= 1;
    }

    flush_rows(rs, cta, runidx, wm, wn, l);
}

// block j: rowsum_j = (row partials of CTAs whose runs cover rb=j)
//                   + (col partials of pairs (rb, d) with (rb+d)&127 == j).
__global__ void __launch_bounds__(128) combine_kernel(float* __restrict__ out) {
    const int j = blockIdx.x;
    const int r = threadIdx.x;
    float sum = 0.f;

    #pragma unroll 4
    for (int c = 0; c < GRID_MAIN; c++) {
        int n0 = (c * NUNITS) / GRID_MAIN;
        int n1 = ((c + 1) * NUNITS) / GRID_MAIN;
        int rb_a, ua, rb_b, ub;
        decode_unit(n0, rb_a, ua);
        decode_unit(n1 - 1, rb_b, ub);
        if (rb_a == j) {
            const float* p = g_rowpart + ((size_t)c * 2 + 0) * 4 * 128;
            sum += (p[r] + p[128 + r]) + (p[256 + r] + p[384 + r]);
        }
        if (rb_b == j && rb_b != rb_a) {
            const float* p = g_rowpart + ((size_t)c * 2 + 1) * 4 * 128;
            sum += (p[r] + p[128 + r]) + (p[256 + r] + p[384 + r]);
        }
    }
    for (int d = 1; d <= 64; d++) {
        int rb = (j - d) & 127;
        if (d <= 63 || rb < 64) {
            const float* p = g_csp + (((size_t)rb * 64 + (d - 1)) * 2) * 128;
            sum += p[r] + p[128 + r];
        }
    }
    float loss = 2.f + logf(sum) - g_pos[j * 128 + r];

    __shared__ float red[128];
    red[r] = loss;
    __syncthreads();
    if (r == 0) {
        float acc = 0.f;
        #pragma unroll 8
        for (int i = 0; i < 128; i++) acc += red[i];
        g_partials[j] = acc;
        __threadfence();
        int old = atomicAdd(&g_cnt, 1);
        if (old == 127) {
            float tot = 0.f;
            for (int i = 0; i < 128; i++) tot += g_partials[i];
            *out = tot / (float)N2;
            g_cnt = 0;   // reset for next graph replay
        }
    }
}

extern "C" void kernel_launch(void* const* d_in, const int* in_sizes, int n_in,
                              void* d_out, int out_size) {
    const float* z = (const float*)d_in[0];
    float* out = (float*)d_out;

    cudaFuncSetAttribute(ntxent_tour_kernel,
                         cudaFuncAttributeMaxDynamicSharedMemorySize, SMEM_BYTES);

    prep_kernel<<<4096, 256>>>(z);
    ntxent_tour_kernel<<<GRID_MAIN, 256, SMEM_BYTES>>>();
    combine_kernel<<<128, 128>>>(out);
}